// round 17
// baseline (speedup 1.0000x reference)
#include <cuda_runtime.h>
#include <cuda_bf16.h>
#include <stdint.h>
#include <math.h>

#define BATCH   8
#define SEQ     4000
#define DIM     256
#define BCH     5
#define NCHUNK  800
#define CG      16
#define NG      50
#define TOKG    (CG*BCH)

#define NEL     (BATCH*SEQ*DIM)      // 8,192,000
#define NEL2    (NEL/2)              // 4,096,000 u32

#define GLOG2 (-0.0196090426f)
__device__ __forceinline__ float gpow(float k) { return exp2f(k * GLOG2); }

// ------------------------- global scratch (no alloc) ------------------------
__device__ uint32_t g_Wsh[3 * 32768], g_Wsl[3 * 32768]; // split weights
__device__ uint32_t g_Qh[NEL2], g_Ql[NEL2];
__device__ uint32_t g_Vh[NEL2], g_Vl[NEL2];
__device__ uint32_t g_Kwh[NEL2], g_Kwl[NEL2];           // pre-weighted K
__device__ float    g_S[(size_t)BATCH * NG * DIM * DIM];
__device__ uint32_t g_Ph[(size_t)BATCH * NG * 32768], g_Pl[(size_t)BATCH * NG * 32768];

// ------------------------------ helpers -------------------------------------
__device__ __forceinline__ unsigned su32(const void* p) {
    return (unsigned)__cvta_generic_to_shared(p);
}
__device__ __forceinline__ void cpa16(unsigned s, const void* g) {
    asm volatile("cp.async.cg.shared.global [%0], [%1], 16;" :: "r"(s), "l"(g));
}
__device__ __forceinline__ void cp_commit() { asm volatile("cp.async.commit_group;"); }
template<int N> __device__ __forceinline__ void cp_wait() {
    asm volatile("cp.async.wait_group %0;" :: "n"(N));
}
__device__ __forceinline__ void ldm4(uint32_t* r, unsigned addr) {
    asm volatile("ldmatrix.sync.aligned.m8n8.x4.shared.b16 {%0,%1,%2,%3}, [%4];"
        : "=r"(r[0]), "=r"(r[1]), "=r"(r[2]), "=r"(r[3]) : "r"(addr));
}
__device__ __forceinline__ void ldm4t(uint32_t* r, unsigned addr) {
    asm volatile("ldmatrix.sync.aligned.m8n8.x4.trans.shared.b16 {%0,%1,%2,%3}, [%4];"
        : "=r"(r[0]), "=r"(r[1]), "=r"(r[2]), "=r"(r[3]) : "r"(addr));
}
__device__ __forceinline__ void mma16816(float* c, const uint32_t* a, const uint32_t* b) {
    asm volatile(
        "mma.sync.aligned.m16n8k16.row.col.f32.bf16.bf16.f32 "
        "{%0,%1,%2,%3},{%4,%5,%6,%7},{%8,%9},{%0,%1,%2,%3};"
        : "+f"(c[0]), "+f"(c[1]), "+f"(c[2]), "+f"(c[3])
        : "r"(a[0]), "r"(a[1]), "r"(a[2]), "r"(a[3]), "r"(b[0]), "r"(b[1]));
}
__device__ __forceinline__ void split2(float x, float y, uint32_t& h, uint32_t& l) {
    __nv_bfloat162 hb = __floats2bfloat162_rn(x, y);
    float rx = x - __bfloat162float(hb.x);
    float ry = y - __bfloat162float(hb.y);
    __nv_bfloat162 lb = __floats2bfloat162_rn(rx, ry);
    h = *reinterpret_cast<uint32_t*>(&hb);
    l = *reinterpret_cast<uint32_t*>(&lb);
}

// ---------------------------------------------------------------------------
// K-1: zero the output (enables commutative atomic accumulation). grid 8000
// ---------------------------------------------------------------------------
__global__ __launch_bounds__(256) void zero_out_kernel(float* __restrict__ out)
{
    int idx = blockIdx.x * 256 + threadIdx.x;
    ((float4*)out)[idx] = make_float4(0.f, 0.f, 0.f, 0.f);
}

// ---------------------------------------------------------------------------
// K0: presplit WEIGHTS only. grid (64,1,3)
// ---------------------------------------------------------------------------
__global__ __launch_bounds__(256) void presplitW_kernel(
    const float* __restrict__ Wq, const float* __restrict__ Wk, const float* __restrict__ Wv)
{
    int which = blockIdx.z;
    const float* s = which == 0 ? Wq : (which == 1 ? Wk : Wv);
    int idx = blockIdx.x * 256 + threadIdx.x;
    float4 v = ((const float4*)s)[idx];
    uint32_t h0, l0, h1, l1;
    split2(v.x, v.y, h0, l0); split2(v.z, v.w, h1, l1);
    ((uint2*)(g_Wsh + which * 32768))[idx] = make_uint2(h0, h1);
    ((uint2*)(g_Wsl + which * 32768))[idx] = make_uint2(l0, l1);
}

// ---------------------------------------------------------------------------
// K1: QKV projections. 512 threads, 128x256 tile. grid (250,1,3)
// ---------------------------------------------------------------------------
#define PJ_STAGE 54272

__device__ __forceinline__ void pj_wcopy(unsigned sb, int tid, int k0,
                                         const char* Bgh, const char* Bgl)
{
#pragma unroll
    for (int j = 0; j < 4; j++) {
        int c = tid + j * 512;
        int seg = c >> 10, cc = c & 1023;
        int r = cc >> 5, ch = cc & 31;
        const char* gp = (seg ? Bgl : Bgh) + ((size_t)(k0 + r) * 256) * 2 + ch * 16;
        cpa16(sb + 20480u + seg * 16896u + r * 528u + ch * 16u, gp);
    }
}

__global__ __launch_bounds__(512) void proj_mma(
    const float* __restrict__ xq, const float* __restrict__ xk, const float* __restrict__ xv)
{
    extern __shared__ char sm[];
    int which = blockIdx.z;
    const float4* A4 = (const float4*)(which == 0 ? xq : (which == 1 ? xk : xv));
    const char* Bgh = (const char*)(g_Wsh + which * 32768);
    const char* Bgl = (const char*)(g_Wsl + which * 32768);
    uint32_t* Ch = which == 0 ? g_Qh : g_Vh;   // unused when which==1
    uint32_t* Cl = which == 0 ? g_Ql : g_Vl;

    int tid = threadIdx.x, lane = tid & 31, wid = tid >> 5;
    int lr = lane & 7, lg = lane >> 3;
    int warp_m = (wid & 1) * 64, warp_n = (wid >> 1) * 32;
    int row0 = blockIdx.x * 128;
    unsigned smB = su32(sm);
    unsigned rowsel = lr + (lg & 1) * 8, colsel = (lg >> 1) * 8;
    unsigned aoff = (unsigned)(warp_m + rowsel) * 80 + colsel * 2;
    unsigned boff = (unsigned)rowsel * 528 + (warp_n + colsel) * 2;

    int r0 = tid >> 3, c0 = tid & 7;
    const float4* Ap0 = A4 + (size_t)(row0 + r0) * 64 + c0;
    const float4* Ap1 = A4 + (size_t)(row0 + r0 + 64) * 64 + c0;

    float acc[4][4][4];
#pragma unroll
    for (int i = 0; i < 4; i++)
#pragma unroll
        for (int j = 0; j < 4; j++)
#pragma unroll
            for (int q = 0; q < 4; q++) acc[i][j][q] = 0.f;

    float4 v0 = Ap0[0], v1 = Ap1[0];
    pj_wcopy(smB, tid, 0, Bgh, Bgl);
    cp_commit();

    for (int it = 0; it < 8; it++) {
        int cur = it & 1;
        float4 n0, n1;
        if (it < 7) {
            n0 = Ap0[(it + 1) * 8];
            n1 = Ap1[(it + 1) * 8];
            pj_wcopy(smB + (1 - cur) * PJ_STAGE, tid, (it + 1) * 32, Bgh, Bgl);
            cp_commit();
        }
        {
            char* sbp = sm + cur * PJ_STAGE;
            uint2* pAh = (uint2*)sbp;
            uint2* pAl = (uint2*)(sbp + 10240);
            uint32_t h0, l0, h1, l1;
            split2(v0.x, v0.y, h0, l0); split2(v0.z, v0.w, h1, l1);
            pAh[r0 * 10 + c0] = make_uint2(h0, h1);
            pAl[r0 * 10 + c0] = make_uint2(l0, l1);
            split2(v1.x, v1.y, h0, l0); split2(v1.z, v1.w, h1, l1);
            pAh[(r0 + 64) * 10 + c0] = make_uint2(h0, h1);
            pAl[(r0 + 64) * 10 + c0] = make_uint2(l0, l1);
        }
        if (it < 7) cp_wait<1>(); else cp_wait<0>();
        __syncthreads();

        unsigned sb = smB + cur * PJ_STAGE;
        unsigned aH = sb + aoff, aL = aH + 10240;
        unsigned bH = sb + 20480 + boff, bL = bH + 16896;
#pragma unroll
        for (int ks = 0; ks < 32; ks += 16) {
            uint32_t ah[4][4], al[4][4], bh[2][4], bl[2][4];
#pragma unroll
            for (int mt = 0; mt < 4; mt++) {
                unsigned o = (unsigned)(mt * 16) * 80 + ks * 2;
                ldm4(ah[mt], aH + o); ldm4(al[mt], aL + o);
            }
#pragma unroll
            for (int np = 0; np < 2; np++) {
                unsigned o = (unsigned)ks * 528 + np * 32;
                ldm4t(bh[np], bH + o); ldm4t(bl[np], bL + o);
            }
#pragma unroll
            for (int mt = 0; mt < 4; mt++)
#pragma unroll
                for (int nt = 0; nt < 4; nt++) {
                    const uint32_t* bhp = &bh[nt >> 1][(nt & 1) * 2];
                    const uint32_t* blp = &bl[nt >> 1][(nt & 1) * 2];
                    mma16816(acc[mt][nt], ah[mt], bhp);
                    mma16816(acc[mt][nt], ah[mt], blp);
                    mma16816(acc[mt][nt], al[mt], bhp);
                }
        }
        __syncthreads();
        v0 = n0; v1 = n1;
    }

    int g4 = lane >> 2, t4 = (lane & 3) * 2;
    bool isK = (which == 1);
#pragma unroll
    for (int mt = 0; mt < 4; mt++)
#pragma unroll
        for (int nt = 0; nt < 4; nt++) {
            int r = row0 + warp_m + mt * 16 + g4;
            int c = warp_n + nt * 8 + t4;
#pragma unroll
            for (int h2 = 0; h2 < 2; h2++) {
                int rr = r + h2 * 8;
                float a0 = acc[mt][nt][h2 * 2], a1 = acc[mt][nt][h2 * 2 + 1];
                uint32_t hh, ll;
                size_t o = ((size_t)rr * 256 + c) >> 1;
                if (isK) {
                    int tok = rr % SEQ;
                    float w = gpow(6.f * (float)(15 - ((tok / 5) & 15)));
                    split2(w * a0, w * a1, hh, ll);
                    g_Kwh[o] = hh; g_Kwl[o] = ll;
                } else {
                    split2(a0, a1, hh, ll);
                    Ch[o] = hh; Cl[o] = ll;
                }
            }
        }
}

// ---------------------------------------------------------------------------
// K2: group states S_g = Kw^T V. Full-group 5-stage prefetch. grid (2,2,400)
// ---------------------------------------------------------------------------
#define GS_STAGE 17408
#define GS_SMEM  (5 * GS_STAGE)

__device__ __forceinline__ void gs_copy(unsigned sb, int tid, size_t bTok, int t0, int d0, int e0)
{
#pragma unroll
    for (int j = 0; j < 4; j++) {
        int c = tid + j * 256;
        int seg = c >> 8, cc = c & 255;
        int r = cc >> 4, ch = cc & 15;
        const char* base = seg == 0 ? (const char*)g_Kwh : seg == 1 ? (const char*)g_Kwl
                         : seg == 2 ? (const char*)g_Vh : (const char*)g_Vl;
        size_t gidx = ((bTok + t0 + r) * 256 + ((seg < 2) ? d0 : e0)) * 2 + ch * 16;
        cpa16(sb + seg * 4352u + r * 272u + ch * 16u, base + gidx);
    }
}

__global__ __launch_bounds__(256) void groupstate_mma()
{
    extern __shared__ char gsm[];
    int bz = blockIdx.z;
    int b = bz / NG, g = bz % NG;
    int d0 = blockIdx.y * 128, e0 = blockIdx.x * 128;
    size_t bTok = (size_t)b * SEQ + (size_t)g * TOKG;

    int tid = threadIdx.x, lane = tid & 31, wid = tid >> 5;
    int lr = lane & 7, lg = lane >> 3;
    int warp_m = (wid & 1) * 64, warp_n = (wid >> 1) * 32;
    unsigned smB = su32(gsm);

    unsigned aoff = ((unsigned)(lr + (lg >> 1) * 8) * 136 + warp_m + (lg & 1) * 8) * 2;
    unsigned boff = ((unsigned)(lr + (lg & 1) * 8) * 136 + warp_n + (lg >> 1) * 8) * 2;

    float acc[4][4][4];
#pragma unroll
    for (int i = 0; i < 4; i++)
#pragma unroll
        for (int j = 0; j < 4; j++)
#pragma unroll
            for (int q = 0; q < 4; q++) acc[i][j][q] = 0.f;

#pragma unroll
    for (int st = 0; st < 5; st++) {
        gs_copy(smB + st * GS_STAGE, tid, bTok, st * 16, d0, e0);
        cp_commit();
    }

#pragma unroll
    for (int it = 0; it < 5; it++) {
        if (it == 0) cp_wait<4>();
        else if (it == 1) cp_wait<3>();
        else if (it == 2) cp_wait<2>();
        else if (it == 3) cp_wait<1>();
        else cp_wait<0>();
        __syncthreads();

        unsigned sb = smB + it * GS_STAGE;
        uint32_t ah[4][4], al[4][4], bh[2][4], bl[2][4];
#pragma unroll
        for (int mt = 0; mt < 4; mt++) {
            unsigned o = (unsigned)(mt * 16) * 2;
            ldm4t(ah[mt], sb + aoff + o); ldm4t(al[mt], sb + 4352 + aoff + o);
        }
#pragma unroll
        for (int np = 0; np < 2; np++) {
            unsigned o = (unsigned)(np * 16) * 2;
            ldm4t(bh[np], sb + 8704 + boff + o); ldm4t(bl[np], sb + 13056 + boff + o);
        }
#pragma unroll
        for (int mt = 0; mt < 4; mt++)
#pragma unroll
            for (int nt = 0; nt < 4; nt++) {
                const uint32_t* bhp = &bh[nt >> 1][(nt & 1) * 2];
                const uint32_t* blp = &bl[nt >> 1][(nt & 1) * 2];
                mma16816(acc[mt][nt], ah[mt], bhp);
                mma16816(acc[mt][nt], ah[mt], blp);
                mma16816(acc[mt][nt], al[mt], bhp);
            }
    }

    int g4 = lane >> 2, t4 = (lane & 3) * 2;
    float* S = g_S + (size_t)bz * DIM * DIM;
#pragma unroll
    for (int mt = 0; mt < 4; mt++)
#pragma unroll
        for (int nt = 0; nt < 4; nt++) {
            int r = d0 + warp_m + mt * 16 + g4;
            int c = e0 + warp_n + nt * 8 + t4;
            *(float2*)&S[(size_t)r * 256 + c] = make_float2(acc[mt][nt][0], acc[mt][nt][1]);
            *(float2*)&S[(size_t)(r + 8) * 256 + c] = make_float2(acc[mt][nt][2], acc[mt][nt][3]);
        }
}

// ---------------------------------------------------------------------------
// K3: exclusive group prefix. 2 floats/thread, 262144 threads, 3-deep ring.
// ---------------------------------------------------------------------------
__global__ __launch_bounds__(256) void prefix_kernel()
{
    int idx = blockIdx.x * 256 + threadIdx.x;
    int b = idx >> 15, de2 = idx & 32767;
    size_t sbase = (size_t)b * NG * 65536 + (size_t)de2 * 2;
    size_t pbase = (size_t)b * NG * 32768 + de2;
    const float g6 = gpow(6.f), g6C = gpow(96.f);

    g_Ph[pbase] = 0u; g_Pl[pbase] = 0u;

    float2 p = make_float2(0.f, 0.f);
    float2 s0 = *(const float2*)&g_S[sbase];
    float2 s1 = *(const float2*)&g_S[sbase + 65536];
    float2 s2 = *(const float2*)&g_S[sbase + 2 * 65536];
    for (int g = 1; g < NG; g++) {
        float2 nxt = s2;
        if (g + 2 < NG) nxt = *(const float2*)&g_S[sbase + (size_t)(g + 2) * 65536];
        p.x = g6 * s0.x + g6C * p.x;
        p.y = g6 * s0.y + g6C * p.y;
        uint32_t h, l;
        split2(p.x, p.y, h, l);
        g_Ph[pbase + (size_t)g * 32768] = h;
        g_Pl[pbase + (size_t)g * 32768] = l;
        s0 = s1; s1 = s2; s2 = nxt;
    }
}

// ---------------------------------------------------------------------------
// K5: per-group local term (2 MMAs). Epilogue accumulates via atomicAdd
// (out pre-zeroed) so ordering vs crossglobal is free. grid (50, 8).
// ---------------------------------------------------------------------------
#define L2_SMEM 98560

__device__ __forceinline__ void l2_qkcopy(unsigned sb, int tid, size_t tokBase, int k0)
{
#pragma unroll
    for (int j = 0; j < 5; j++) {
        int c = tid + j * 256;
        int seg = c / 320, cc = c - seg * 320;
        int r = cc >> 2, ch = cc & 3;
        const char* base = seg == 0 ? (const char*)g_Qh : seg == 1 ? (const char*)g_Ql
                         : seg == 2 ? (const char*)g_Kwh : (const char*)g_Kwl;
        cpa16(sb + seg * 6400u + r * 80u + ch * 16u,
              base + ((tokBase + r) * 256 + k0) * 2 + ch * 16);
    }
}
__device__ __forceinline__ void l2_vcopy(unsigned smB, int tid, size_t tokBase, int e0)
{
#pragma unroll
    for (int j = 0; j < 10; j++) {
        int c = tid + j * 256;
        int seg = c / 1280, cc = c - seg * 1280;
        int r = cc >> 4, ch = cc & 15;
        const char* base = seg ? (const char*)g_Vl : (const char*)g_Vh;
        cpa16(smB + 55040u + seg * 21760u + r * 272u + ch * 16u,
              base + ((tokBase + r) * 256 + e0) * 2 + ch * 16);
    }
}

__global__ __launch_bounds__(256) void local2_kernel(float* __restrict__ out)
{
    extern __shared__ char sm[];
    float* sS = (float*)sm;                       // [80][84]
    uint32_t* sMh = (uint32_t*)(sm + 26880);      // [80][44]
    uint32_t* sMl = (uint32_t*)(sm + 40960);

    int g = blockIdx.x, b = blockIdx.y;
    int tid = threadIdx.x, lane = tid & 31, wid = tid >> 5;
    int lr = lane & 7, lg = lane >> 3;
    int g4 = lane >> 2, t4 = (lane & 3) * 2;
    unsigned smB = su32(sm);

    const size_t tokBase = (size_t)b * SEQ + (size_t)g * TOKG;

    unsigned rowsel = lr + (lg & 1) * 8;
    unsigned colsel = (lg >> 1) * 8;

    float acc1[4][2][4];
#pragma unroll
    for (int i = 0; i < 4; i++)
#pragma unroll
        for (int j = 0; j < 2; j++)
#pragma unroll
            for (int q = 0; q < 4; q++) acc1[i][j][q] = 0.f;

    l2_qkcopy(smB + 26880, tid, tokBase, 0);
    cp_commit();

    for (int it = 0; it < 8; it++) {
        int cur = it & 1;
        if (it < 7) {
            l2_qkcopy(smB + 26880 + (1 - cur) * 25600, tid, tokBase, (it + 1) * 32);
            cp_commit();
            cp_wait<1>();
        } else cp_wait<0>();
        __syncthreads();

        unsigned sb = smB + 26880 + cur * 25600;
        unsigned qH = sb + rowsel * 80 + colsel * 2, qL = qH + 6400;
        unsigned kH = qH + 12800, kL = qH + 19200;
#pragma unroll
        for (int ks = 0; ks < 32; ks += 16) {
            int li = 0;
            for (int tile = wid; tile < 25; tile += 8, li++) {
                int mt = tile / 5, nt = tile - mt * 5;
                unsigned ao = (unsigned)(mt * 16) * 80 + ks * 2;
                unsigned bo = (unsigned)(nt * 16) * 80 + ks * 2;
                uint32_t ah[4], al[4], rh[4], rl[4];
                ldm4(ah, qH + ao); ldm4(al, qL + ao);
                ldm4(rh, kH + bo); ldm4(rl, kL + bo);
                uint32_t bh0[2] = {rh[0], rh[2]}, bh1[2] = {rh[1], rh[3]};
                uint32_t bl0[2] = {rl[0], rl[2]}, bl1[2] = {rl[1], rl[3]};
                mma16816(acc1[li][0], ah, bh0);
                mma16816(acc1[li][0], ah, bl0);
                mma16816(acc1[li][0], al, bh0);
                mma16816(acc1[li][1], ah, bh1);
                mma16816(acc1[li][1], ah, bl1);
                mma16816(acc1[li][1], al, bh1);
            }
        }
        __syncthreads();
    }

    {
        int li = 0;
        for (int tile = wid; tile < 25; tile += 8, li++) {
            int mt = tile / 5, nt = tile - mt * 5;
#pragma unroll
            for (int sub = 0; sub < 2; sub++) {
                int c = nt * 16 + sub * 8 + t4;
                int r = mt * 16 + g4;
                sS[r * 84 + c]     = acc1[li][sub][0];
                sS[r * 84 + c + 1] = acc1[li][sub][1];
                sS[(r + 8) * 84 + c]     = acc1[li][sub][2];
                sS[(r + 8) * 84 + c + 1] = acc1[li][sub][3];
            }
        }
    }
    __syncthreads();

    l2_vcopy(smB, tid, tokBase, 0);
    cp_commit();

    for (int pz = tid; pz < 3200; pz += 256) {
        int t = pz / 40, sp = pz - t * 40;
        int i = t / 5, o = t - i * 5;
        float mv[2];
#pragma unroll
        for (int u = 0; u < 2; u++) {
            int s = sp * 2 + u;
            int j = s / 5, p = s - j * 5;
            float v = 0.f;
            if (j == i && p <= o) v += gpow((float)(p - o - 6 * (15 - i))) * sS[t * 84 + s];
            if (i < 15 && j <= i) v += gpow((float)(6 * (i - 14))) * sS[(t + 5) * 84 + s];
            mv[u] = v;
        }
        uint32_t h, l;
        split2(mv[0], mv[1], h, l);
        sMh[t * 44 + sp] = h;
        sMl[t * 44 + sp] = l;
    }

    unsigned mH = smB + 26880 + rowsel * 176 + colsel * 2, mL = mH + 14080;
    unsigned vH = smB + 55040 + rowsel * 272 + wid * 32 + colsel * 2, vL = vH + 21760;

#pragma unroll
    for (int pass = 0; pass < 2; pass++) {
        int e0 = pass * 128;
        cp_wait<0>();
        __syncthreads();

        float acc2[5][2][4];
#pragma unroll
        for (int i = 0; i < 5; i++)
#pragma unroll
            for (int j = 0; j < 2; j++)
#pragma unroll
                for (int q = 0; q < 4; q++) acc2[i][j][q] = 0.f;

#pragma unroll
        for (int ks = 0; ks < 80; ks += 16) {
            uint32_t bh[4], bl[4];
            unsigned vo = (unsigned)ks * 272;
            ldm4t(bh, vH + vo); ldm4t(bl, vL + vo);
#pragma unroll
            for (int mt = 0; mt < 5; mt++) {
                unsigned ao = (unsigned)(mt * 16) * 176 + ks * 2;
                uint32_t ah[4], al[4];
                ldm4(ah, mH + ao); ldm4(al, mL + ao);
                mma16816(acc2[mt][0], ah, &bh[0]);
                mma16816(acc2[mt][0], ah, &bl[0]);
                mma16816(acc2[mt][0], al, &bh[0]);
                mma16816(acc2[mt][1], ah, &bh[2]);
                mma16816(acc2[mt][1], ah, &bl[2]);
                mma16816(acc2[mt][1], al, &bh[2]);
            }
        }
        __syncthreads();
        if (pass == 0) {
            l2_vcopy(smB, tid, tokBase, 128);
            cp_commit();
        }

#pragma unroll
        for (int mt = 0; mt < 5; mt++)
#pragma unroll
            for (int nt = 0; nt < 2; nt++) {
                int r = mt * 16 + g4;
                int c = e0 + wid * 16 + nt * 8 + t4;
                float* O0 = out + (tokBase + r) * 256 + c;
                float* O1 = out + (tokBase + r + 8) * 256 + c;
                atomicAdd(O0,     acc2[mt][nt][0]);
                atomicAdd(O0 + 1, acc2[mt][nt][1]);
                atomicAdd(O1,     acc2[mt][nt][2]);
                atomicAdd(O1 + 1, acc2[mt][nt][3]);
            }
    }
}

// ---------------------------------------------------------------------------
// K4: global cross: out += scale * Q_group @ P_g via REDG atomics. grid (2,400)
// ---------------------------------------------------------------------------
#define CGX_SMEM 60416

__device__ __forceinline__ void cg_copy(unsigned sb, int tid, size_t qTok, size_t pBase, int k0, int e0)
{
#pragma unroll
    for (int j = 0; j < 7; j++) {
        int c = tid + j * 256;
        if (c >= 1664) break;
        if (c < 640) {
            int seg = c / 320, cc = c - seg * 320;
            int r = cc >> 2, ch = cc & 3;
            const char* base = seg ? (const char*)g_Ql : (const char*)g_Qh;
            cpa16(sb + seg * 6400u + r * 80u + ch * 16u,
                  base + ((qTok + r) * 256 + k0) * 2 + ch * 16);
        } else {
            int cc = c - 640;
            int seg = cc >> 9, c2 = cc & 511;
            int r = c2 >> 4, ch = c2 & 15;
            const char* base = seg ? (const char*)g_Pl : (const char*)g_Ph;
            cpa16(sb + 12800u + seg * 8704u + r * 272u + ch * 16u,
                  base + (pBase + (size_t)(k0 + r) * 256 + e0) * 2 + ch * 16);
        }
    }
}

__global__ __launch_bounds__(256) void crossglobal_mma(float* __restrict__ out)
{
    extern __shared__ char sm[];
    int bz = blockIdx.y;
    int b = bz / NG, g = bz % NG;
    int e0 = blockIdx.x * 128;
    size_t qTok = (size_t)b * SEQ + (size_t)g * TOKG;
    size_t pBase = (size_t)bz * 65536;

    int tid = threadIdx.x, lane = tid & 31, wid = tid >> 5;
    int lr = lane & 7, lg = lane >> 3;
    int warp_n = wid * 16;
    unsigned smB = su32(sm);

    unsigned rowsel = lr + (lg & 1) * 8, colsel = (lg >> 1) * 8;
    unsigned aoff = rowsel * 80 + colsel * 2;
    unsigned boff = rowsel * 272 + (warp_n + colsel) * 2;

    float acc[5][2][4];
#pragma unroll
    for (int i = 0; i < 5; i++)
#pragma unroll
        for (int j = 0; j < 2; j++)
#pragma unroll
            for (int q = 0; q < 4; q++) acc[i][j][q] = 0.f;

    cg_copy(smB, tid, qTok, pBase, 0, e0);
    cp_commit();

    for (int it = 0; it < 8; it++) {
        int cur = it & 1;
        if (it < 7) {
            cg_copy(smB + (1 - cur) * 30208, tid, qTok, pBase, (it + 1) * 32, e0);
            cp_commit();
            cp_wait<1>();
        } else cp_wait<0>();
        __syncthreads();

        unsigned sb = smB + cur * 30208;
        unsigned aH = sb + aoff, aL = aH + 6400;
        unsigned bH = sb + 12800 + boff, bL = bH + 8704;
#pragma unroll
        for (int ks = 0; ks < 32; ks += 16) {
            uint32_t ah[5][4], al[5][4], bh[4], bl[4];
#pragma unroll
            for (int mt = 0; mt < 5; mt++) {
                unsigned o = (unsigned)(mt * 16) * 80 + ks * 2;
                ldm4(ah[mt], aH + o); ldm4(al[mt], aL + o);
            }
            {
                unsigned o = (unsigned)ks * 272;
                ldm4t(bh, bH + o); ldm4t(bl, bL + o);
            }
#pragma unroll
            for (int mt = 0; mt < 5; mt++)
#pragma unroll
                for (int nt = 0; nt < 2; nt++) {
                    const uint32_t* bhp = &bh[nt * 2];
                    const uint32_t* blp = &bl[nt * 2];
                    mma16816(acc[mt][nt], ah[mt], bhp);
                    mma16816(acc[mt][nt], ah[mt], blp);
                    mma16816(acc[mt][nt], al[mt], bhp);
                }
        }
        __syncthreads();
    }

    int g4 = lane >> 2, t4 = (lane & 3) * 2;
#pragma unroll
    for (int mt = 0; mt < 5; mt++)
#pragma unroll
        for (int nt = 0; nt < 2; nt++) {
            int c = e0 + warp_n + nt * 8 + t4;
            int r1 = mt * 16 + g4;
            int tok1 = g * TOKG + r1 - 5;
            if (tok1 >= 0) {
                float s = gpow((float)(6 * (r1 / 5)));
                float* p = &out[((size_t)b * SEQ + tok1) * 256 + c];
                atomicAdd(p,     s * acc[mt][nt][0]);
                atomicAdd(p + 1, s * acc[mt][nt][1]);
            }
            int r2 = r1 + 8;
            int tok2 = g * TOKG + r2 - 5;
            if (tok2 >= 0) {
                float s = gpow((float)(6 * (r2 / 5)));
                float* p = &out[((size_t)b * SEQ + tok2) * 256 + c];
                atomicAdd(p,     s * acc[mt][nt][2]);
                atomicAdd(p + 1, s * acc[mt][nt][3]);
            }
        }
}

// ---------------------------------------------------------------------------
// Launch DAG (capture-safe — s1 is FORKED from the origin stream via evFork
// BEFORE any s1 work, per stream-capture rules):
//   s0: evFork -> presplitW -> proj -> evProj -> groupstate -> prefix
//       -> [wait evZ] crossglobal -> [wait evL2] (join)
//   s1: [wait evFork] zero(out) -> evZ ; [wait evProj] local2 -> evL2
// ---------------------------------------------------------------------------
extern "C" void kernel_launch(void* const* d_in, const int* in_sizes, int n_in,
                              void* d_out, int out_size)
{
    const float* xq = (const float*)d_in[0];
    const float* xk = (const float*)d_in[1];
    const float* xv = (const float*)d_in[2];
    const float* Wq = (const float*)d_in[3];
    const float* Wk = (const float*)d_in[4];
    const float* Wv = (const float*)d_in[5];
    float* out = (float*)d_out;

    static cudaStream_t s1;
    static cudaEvent_t evFork, evProj, evL2, evZ;
    static int inited = 0;
    if (!inited) {
        cudaFuncSetAttribute(proj_mma, cudaFuncAttributeMaxDynamicSharedMemorySize, 2 * PJ_STAGE);
        cudaFuncSetAttribute(groupstate_mma, cudaFuncAttributeMaxDynamicSharedMemorySize, GS_SMEM);
        cudaFuncSetAttribute(local2_kernel, cudaFuncAttributeMaxDynamicSharedMemorySize, L2_SMEM);
        cudaFuncSetAttribute(crossglobal_mma, cudaFuncAttributeMaxDynamicSharedMemorySize, CGX_SMEM);
        cudaStreamCreateWithFlags(&s1, cudaStreamNonBlocking);
        cudaEventCreateWithFlags(&evFork, cudaEventDisableTiming);
        cudaEventCreateWithFlags(&evProj, cudaEventDisableTiming);
        cudaEventCreateWithFlags(&evL2, cudaEventDisableTiming);
        cudaEventCreateWithFlags(&evZ, cudaEventDisableTiming);
        inited = 1;
    }

    // fork s1 from the capture-origin stream FIRST
    cudaEventRecord(evFork, 0);
    cudaStreamWaitEvent(s1, evFork, 0);

    // s1: zero output early (overlaps presplit/proj)
    zero_out_kernel<<<dim3(8000), 256, 0, s1>>>(out);
    cudaEventRecord(evZ, s1);

    // s0: presplit + unified QKV projection
    presplitW_kernel<<<dim3(64, 1, 3), 256>>>(Wq, Wk, Wv);
    proj_mma<<<dim3(250, 1, 3), 512, 2 * PJ_STAGE>>>(xq, xk, xv);
    cudaEventRecord(evProj, 0);

    // s1: local term (atomic accumulate) — off the critical path
    cudaStreamWaitEvent(s1, evProj, 0);
    local2_kernel<<<dim3(NG, BATCH), 256, L2_SMEM, s1>>>(out);
    cudaEventRecord(evL2, s1);

    // s0: memory-bound chain, then cross term (needs only zero + prefix)
    groupstate_mma<<<dim3(2, 2, BATCH * NG), 256, GS_SMEM>>>();
    prefix_kernel<<<dim3(1024), 256>>>();
    cudaStreamWaitEvent(0, evZ, 0);
    crossglobal_mma<<<dim3(2, BATCH * NG), 256, CGX_SMEM>>>(out);

    // join s1 so the harness's stream sees all work complete
    cudaStreamWaitEvent(0, evL2, 0);
}